// round 4
// baseline (speedup 1.0000x reference)
#include <cuda_runtime.h>

typedef unsigned long long u64;

#define B_  512
#define T_  512
#define F_  13
#define H_  128
#define O1_ 64
#define NT  384   // 8 rec warps + 4 fc warps

__device__ __forceinline__ u64 fma2(u64 a, u64 b, u64 c) {
    u64 d;
    asm("fma.rn.f32x2 %0, %1, %2, %3;" : "=l"(d) : "l"(a), "l"(b), "l"(c));
    return d;
}
__device__ __forceinline__ float f2sum(u64 a) {
    float lo, hi;
    asm("mov.b64 {%0, %1}, %2;" : "=f"(lo), "=f"(hi) : "l"(a));
    return lo + hi;
}
__device__ __forceinline__ u64 pack2(float lo, float hi) {
    u64 r;
    asm("mov.b64 %0, {%1, %2};" : "=l"(r) : "f"(lo), "f"(hi));
    return r;
}
// tanh(x) = 1 - 2/(1+e^{2x}); abs err ~1e-7, inf-safe.
__device__ __forceinline__ float tanh_fast(float x) {
    float e = __expf(2.f * x);
    return 1.f - __fdividef(2.f, 1.f + e);
}
__device__ __forceinline__ void barsync() {
    asm volatile("bar.sync 0;" ::: "memory");
}

// ---------------------------------------------------------------------------
// Fused persistent RNN, 128 CTAs x 384 threads, 4 batch rows per CTA.
//   threads   0..255 (warps 0-7): recurrence, k-split.
//       thread (j = tid&127, h = tid>>7) holds W_hh[j][64h : 64h+64) in regs,
//       computes partial dots for all 4 rows over its k-half.
//       Cross partials (for the other half's 2 rows) go through smem Ps;
//       each half finishes (combine + tanh + store Hs) its own 2 rows after barB.
//   threads 256..383 (warps 8-11): fc1(relu)+fc2(sigmoid), one step behind,
//       thread (o = ft&63, rp = ft>>6) holds fc1_w[o][:] in regs.
// Two bar.sync per loop iteration in every role (counting barrier pairing).
// ---------------------------------------------------------------------------
__global__ void __launch_bounds__(NT, 1) rnn_fused(
    const float* __restrict__ x,
    const float* __restrict__ W_ih,
    const float* __restrict__ W_hh,
    const float* __restrict__ b_ih,
    const float* __restrict__ b_hh,
    const float* __restrict__ fc1_w,
    const float* __restrict__ fc1_b,
    const float* __restrict__ fc2_w,
    const float* __restrict__ fc2_b,
    float* __restrict__ out)
{
    __shared__ __align__(16) float Hs[4 * H_];      // h state, 4 rows
    __shared__ __align__(16) float Xs[4 * 16];      // x(t), padded 13->16
    __shared__ __align__(8)  float Ps[2 * H_ * 2];  // cross k-half partials
    __shared__ float red[8];

    const int tid  = threadIdx.x;
    const int row0 = blockIdx.x * 4;

    // ---- convergent init ----
    if (tid < H_) {
#pragma unroll
        for (int r = 0; r < 4; r++) Hs[r * H_ + tid] = 0.f;
    }
    if (tid < 64) Xs[tid] = 0.f;
    __syncthreads();
    {
        int ft = tid - 256;
        if (ft >= 0 && ft < 52) {
            int pr = ft / 13, pf = ft - pr * 13;
            Xs[pr * 16 + pf] = x[((size_t)(row0 + pr) * T_) * F_ + pf];
        }
    }
    __syncthreads();

    if (tid < 256) {
        // =================== RECURRENCE (k-split) ===================
        const int j    = tid & 127;
        const int h    = tid >> 7;        // k-half: 0 or 1
        const int koff = h * 64;
        const int own0 = 2 * h;           // rows this half finalizes
        const int oth0 = 2 * (1 - h);     // rows whose partials go to smem

        u64 w[32];
        {
            const ulonglong2* wrow =
                (const ulonglong2*)(W_hh + (size_t)j * H_ + koff);
#pragma unroll
            for (int m = 0; m < 16; m++) {
                ulonglong2 v = wrow[m];
                w[2 * m] = v.x; w[2 * m + 1] = v.y;
            }
        }
        u64 wihp[8];
        {
            float wih[16];
#pragma unroll
            for (int f = 0; f < 16; f++)
                wih[f] = (f < F_) ? __ldg(W_ih + j * F_ + f) : 0.f;
#pragma unroll
            for (int q = 0; q < 8; q++)
                wihp[q] = pack2(wih[2 * q], wih[2 * q + 1]);
        }
        const float bsum = __ldg(b_ih + j) + __ldg(b_hh + j);

        float2* PsW = (float2*)(Ps + (h * H_ + j) * 2);        // write
        const float2* PsR = (const float2*)(Ps + ((1 - h) * H_ + j) * 2); // read

        float own_s0 = 0.f, own_s1 = 0.f;

        for (int t = 0; t <= T_; t++) {
            if (t < T_) {
                u64 a0[4], a1[4];
#pragma unroll
                for (int r = 0; r < 4; r++) { a0[r] = 0ull; a1[r] = 0ull; }

                // input projection for the 2 rows this half owns
#pragma unroll
                for (int ri = 0; ri < 2; ri++) {
                    const int r = own0 + ri;
                    const ulonglong2* xr = (const ulonglong2*)(Xs + r * 16);
                    ulonglong2 xa = xr[0], xb = xr[1], xc = xr[2], xd = xr[3];
                    a0[r] = fma2(xa.x, wihp[0], a0[r]);
                    a1[r] = fma2(xa.y, wihp[1], a1[r]);
                    a0[r] = fma2(xb.x, wihp[2], a0[r]);
                    a1[r] = fma2(xb.y, wihp[3], a1[r]);
                    a0[r] = fma2(xc.x, wihp[4], a0[r]);
                    a1[r] = fma2(xc.y, wihp[5], a1[r]);
                    a0[r] = fma2(xd.x, wihp[6], a0[r]);
                    a1[r] = fma2(xd.y, wihp[7], a1[r]);
                }

                // recurrence over this thread's k-half (broadcast LDS)
#pragma unroll
                for (int m = 0; m < 16; m++) {
                    ulonglong2 h0 = *(const ulonglong2*)(Hs + 0 * H_ + koff + 4 * m);
                    ulonglong2 h1 = *(const ulonglong2*)(Hs + 1 * H_ + koff + 4 * m);
                    ulonglong2 h2 = *(const ulonglong2*)(Hs + 2 * H_ + koff + 4 * m);
                    ulonglong2 h3 = *(const ulonglong2*)(Hs + 3 * H_ + koff + 4 * m);
                    a0[0] = fma2(h0.x, w[2 * m], a0[0]);
                    a0[1] = fma2(h1.x, w[2 * m], a0[1]);
                    a0[2] = fma2(h2.x, w[2 * m], a0[2]);
                    a0[3] = fma2(h3.x, w[2 * m], a0[3]);
                    a1[0] = fma2(h0.y, w[2 * m + 1], a1[0]);
                    a1[1] = fma2(h1.y, w[2 * m + 1], a1[1]);
                    a1[2] = fma2(h2.y, w[2 * m + 1], a1[2]);
                    a1[3] = fma2(h3.y, w[2 * m + 1], a1[3]);
                }

                // own rows: carry across barrier (bias folded in)
                own_s0 = bsum + f2sum(a0[own0])     + f2sum(a1[own0]);
                own_s1 = bsum + f2sum(a0[own0 + 1]) + f2sum(a1[own0 + 1]);
                // other half's rows: partials to smem
                float p0 = f2sum(a0[oth0])     + f2sum(a1[oth0]);
                float p1 = f2sum(a0[oth0 + 1]) + f2sum(a1[oth0 + 1]);
                *PsW = make_float2(p0, p1);
            }
            barsync();   // B: all reads of Hs/Xs done; Ps visible
            if (t < T_) {
                float2 p = *PsR;
                float hn0 = tanh_fast(own_s0 + p.x);
                float hn1 = tanh_fast(own_s1 + p.y);
                Hs[own0 * H_ + j]       = hn0;
                Hs[(own0 + 1) * H_ + j] = hn1;
            }
            barsync();   // A: new Hs/Xs visible
        }
    } else {
        // =================== FC HALF ===================
        const int ft = tid - 256;
        const int o  = ft & 63;          // fc1 output index
        const int rp = ft >> 6;          // rows {2rp, 2rp+1}
        const int wloc = ft >> 5;        // 0..3 local warp
        const int lane = ft & 31;

        u64 fw[64];
        {
            const ulonglong2* fr = (const ulonglong2*)(fc1_w + (size_t)o * H_);
#pragma unroll
            for (int m = 0; m < 32; m++) {
                ulonglong2 v = fr[m];
                fw[2 * m] = v.x; fw[2 * m + 1] = v.y;
            }
        }
        const float b1 = __ldg(fc1_b + o);
        const float w2 = __ldg(fc2_w + o);
        const float b2 = __ldg(fc2_b);

        const bool is_loader = (ft < 52);
        const int  pr = ft / 13, pf = ft - pr * 13;
        const float* xptr = x + ((size_t)(row0 + pr) * T_) * F_ + pf;

        const float* h0p = Hs + (2 * rp) * H_;
        const float* h1p = Hs + (2 * rp + 1) * H_;

        for (int t = 0; t <= T_; t++) {
            float xn = 0.f;
            if (is_loader && t < T_) {
                int tn = (t + 1 < T_) ? (t + 1) : t;
                xn = __ldg(xptr + (size_t)tn * F_);
            }

            if (t > 0) {
                // Hs holds h(t-1)
                u64 a0 = 0ull, a1 = 0ull, c0 = 0ull, c1 = 0ull;
#pragma unroll
                for (int m = 0; m < 32; m++) {
                    ulonglong2 hv0 = *(const ulonglong2*)(h0p + 4 * m);
                    ulonglong2 hv1 = *(const ulonglong2*)(h1p + 4 * m);
                    a0 = fma2(hv0.x, fw[2 * m],     a0);
                    a1 = fma2(hv0.y, fw[2 * m + 1], a1);
                    c0 = fma2(hv1.x, fw[2 * m],     c0);
                    c1 = fma2(hv1.y, fw[2 * m + 1], c1);
                }
                float y0 = fmaxf(f2sum(a0) + f2sum(a1) + b1, 0.f);
                float y1 = fmaxf(f2sum(c0) + f2sum(c1) + b1, 0.f);
                float part0 = y0 * w2;
                float part1 = y1 * w2;
#pragma unroll
                for (int off = 16; off > 0; off >>= 1) {
                    part0 += __shfl_xor_sync(0xffffffffu, part0, off);
                    part1 += __shfl_xor_sync(0xffffffffu, part1, off);
                }
                if (lane == 0) {
                    red[wloc * 2 + 0] = part0;
                    red[wloc * 2 + 1] = part1;
                }
            }
            barsync();   // B
            if (is_loader && t < T_) Xs[pr * 16 + pf] = xn;
            if (t > 0 && ft < 4) {
                int r = ft;
                int i1 = (r >> 1) * 4 + (r & 1);
                float s = red[i1] + red[i1 + 2] + b2;
                out[(size_t)(row0 + r) * T_ + (t - 1)] =
                    __fdividef(1.f, 1.f + __expf(-s));
            }
            barsync();   // A
        }
    }
}

// ---------------------------------------------------------------------------

extern "C" void kernel_launch(void* const* d_in, const int* in_sizes, int n_in,
                              void* d_out, int out_size)
{
    const float* x     = (const float*)d_in[0];
    const float* W_ih  = (const float*)d_in[1];
    const float* W_hh  = (const float*)d_in[2];
    const float* b_ih  = (const float*)d_in[3];
    const float* b_hh  = (const float*)d_in[4];
    const float* fc1_w = (const float*)d_in[5];
    const float* fc1_b = (const float*)d_in[6];
    const float* fc2_w = (const float*)d_in[7];
    const float* fc2_b = (const float*)d_in[8];
    float* out = (float*)d_out;

    rnn_fused<<<128, NT>>>(x, W_ih, W_hh, b_ih, b_hh,
                           fc1_w, fc1_b, fc2_w, fc2_b, out);
}

// round 6
// speedup vs baseline: 1.0339x; 1.0339x over previous
#include <cuda_runtime.h>

typedef unsigned long long u64;

#define B_  512
#define T_  512
#define F_  13
#define H_  128
#define O1_ 64
#define NT  256

__device__ __forceinline__ u64 fma2(u64 a, u64 b, u64 c) {
    u64 d;
    asm("fma.rn.f32x2 %0, %1, %2, %3;" : "=l"(d) : "l"(a), "l"(b), "l"(c));
    return d;
}
__device__ __forceinline__ float f2sum(u64 a) {
    float lo, hi;
    asm("mov.b64 {%0, %1}, %2;" : "=f"(lo), "=f"(hi) : "l"(a));
    return lo + hi;
}
__device__ __forceinline__ u64 pack2(float lo, float hi) {
    u64 r;
    asm("mov.b64 %0, {%1, %2};" : "=l"(r) : "f"(lo), "f"(hi));
    return r;
}
// tanh(x) = 1 - 2/(1+e^{2x}); abs err ~1e-7, inf-safe.
__device__ __forceinline__ float tanh_fast(float x) {
    float e = __expf(2.f * x);
    return 1.f - __fdividef(2.f, 1.f + e);
}
__device__ __forceinline__ float sigmoid_fast(float s) {
    return __fdividef(1.f, 1.f + __expf(-s));
}

// ---------------------------------------------------------------------------
// Fused persistent RNN, 128 CTAs x 256 threads, 4 batch rows per CTA.
// Homogeneous warps: EVERY thread does a slice of the recurrence AND a slice
// of the fc head each step; the independent fc FMAs hide the rec chain's
// latency within the same warp.
//
// Recurrence (k-split):  thread (j = tid&127, hh = tid>>7) holds
//   W_hh[j][64hh : 64hh+64) in regs, computes partial dots for all 4 rows
//   over its k-half. Cross-half partials exchanged via Ps; each half
//   finalizes (tanh + store) its own 2 rows post-barrier.
// FC head (o-q split):   thread (o = tid&63, q = tid>>6) holds
//   fc1_w[o][32q : 32q+32) in regs; at iteration t (>=1) computes quarter-
//   dots on h(t) — the SAME stable buffer Hrd the recurrence reads —
//   producing output index t-1. Partials -> Pfc[r][q][o]; post-barrier,
//   thread (r=q, o) combines 4 quarters, relu, *fc2_w[o], bfly-reduce per
//   warp; odd warp drops its half in red[r], even warp carries its half in a
//   register and emits sigmoid+STG at the top of the NEXT iteration.
// Two __syncthreads per step.
// ---------------------------------------------------------------------------
__global__ void __launch_bounds__(NT, 1) rnn_fused(
    const float* __restrict__ x,
    const float* __restrict__ W_ih,
    const float* __restrict__ W_hh,
    const float* __restrict__ b_ih,
    const float* __restrict__ b_hh,
    const float* __restrict__ fc1_w,
    const float* __restrict__ fc1_b,
    const float* __restrict__ fc2_w,
    const float* __restrict__ fc2_b,
    float* __restrict__ out)
{
    __shared__ __align__(16) float Hs[2][4 * H_];   // double-buffered h
    __shared__ __align__(16) float Xs[4 * 16];      // x(t), padded 13->16
    __shared__ __align__(8)  float Ps[2 * H_ * 2];  // rec cross k-half partials
    __shared__ __align__(16) float Pfc[4 * 4 * 64]; // fc partials [r][q][o]
    __shared__ float red[4];

    const int tid  = threadIdx.x;
    const int lane = tid & 31;
    const int warp = tid >> 5;
    const int row0 = blockIdx.x * 4;

    // ---- init ----
    for (int i = tid; i < 2 * 4 * H_; i += NT) ((float*)Hs)[i] = 0.f;
    if (tid < 64) Xs[tid] = 0.f;
    __syncthreads();
    const bool is_loader = (tid < 52);
    const int  pr = tid / 13, pf = tid - pr * 13;
    if (is_loader)
        Xs[pr * 16 + pf] = x[((size_t)(row0 + pr) * T_) * F_ + pf];
    __syncthreads();

    // ---- recurrence weights (k-split) ----
    const int j    = tid & 127;
    const int hh   = tid >> 7;
    const int koff = hh * 64;
    const int own0 = 2 * hh;
    const int oth0 = 2 - 2 * hh;

    u64 w[32];
    {
        const ulonglong2* wrow = (const ulonglong2*)(W_hh + (size_t)j * H_ + koff);
#pragma unroll
        for (int m = 0; m < 16; m++) {
            ulonglong2 v = wrow[m];
            w[2 * m] = v.x; w[2 * m + 1] = v.y;
        }
    }
    u64 wihp[8];
    {
        float wih[16];
#pragma unroll
        for (int f = 0; f < 16; f++)
            wih[f] = (f < F_) ? __ldg(W_ih + j * F_ + f) : 0.f;
#pragma unroll
        for (int q = 0; q < 8; q++)
            wihp[q] = pack2(wih[2 * q], wih[2 * q + 1]);
    }
    const float bsum = __ldg(b_ih + j) + __ldg(b_hh + j);

    // ---- fc weights (o-q split) ----
    const int o = tid & 63;
    const int q = tid >> 6;          // quarter index AND combine-row index
    u64 fw[16];
    {
        const ulonglong2* fr =
            (const ulonglong2*)(fc1_w + (size_t)o * H_ + 32 * q);
#pragma unroll
        for (int m = 0; m < 8; m++) {
            ulonglong2 v = fr[m];
            fw[2 * m] = v.x; fw[2 * m + 1] = v.y;
        }
    }
    const float b1 = __ldg(fc1_b + o);
    const float w2 = __ldg(fc2_w + o);
    const float b2 = __ldg(fc2_b);
    const bool evenw = ((warp & 1) == 0);
    const int  rC = q;               // output row this thread combines/stores

    float2* PsW = (float2*)(Ps + (hh * H_ + j) * 2);
    const float2* PsR = (const float2*)(Ps + ((1 - hh) * H_ + j) * 2);

    const float* xptr = x + ((size_t)(row0 + pr) * T_) * F_ + pf;
    float* outp = out + (size_t)(row0 + rC) * T_;

    int cur = 0;
    float own_s0 = 0.f, own_s1 = 0.f, carry = 0.f;

    for (int t = 0; t <= T_; t++) {
        // ---- emit output (t-2): combined last iteration ----
        if (t >= 2 && evenw && lane == 0)
            outp[t - 2] = sigmoid_fast(carry + red[rC] + b2);

        const float* Hrd = Hs[cur];   // h(t): stable since barrier A of t-1

        float xn = 0.f;
        if (is_loader && t < T_) {
            int tn = (t + 1 < T_) ? (t + 1) : t;
            xn = __ldg(xptr + (size_t)tn * F_);
        }

        // ================== pre-barrier compute ==================
        if (t < T_) {
            u64 a0[4], a1[4];
#pragma unroll
            for (int r = 0; r < 4; r++) { a0[r] = 0ull; a1[r] = 0ull; }

            // input projection for the 2 rows this k-half owns
#pragma unroll
            for (int ri = 0; ri < 2; ri++) {
                const int r = own0 + ri;
                const ulonglong2* xr = (const ulonglong2*)(Xs + r * 16);
                ulonglong2 xa = xr[0], xb = xr[1], xc = xr[2], xd = xr[3];
                a0[r] = fma2(xa.x, wihp[0], a0[r]);
                a1[r] = fma2(xa.y, wihp[1], a1[r]);
                a0[r] = fma2(xb.x, wihp[2], a0[r]);
                a1[r] = fma2(xb.y, wihp[3], a1[r]);
                a0[r] = fma2(xc.x, wihp[4], a0[r]);
                a1[r] = fma2(xc.y, wihp[5], a1[r]);
                a0[r] = fma2(xd.x, wihp[6], a0[r]);
                a1[r] = fma2(xd.y, wihp[7], a1[r]);
            }
            // recurrence partial over this thread's k-half (broadcast LDS)
#pragma unroll
            for (int m = 0; m < 16; m++) {
                ulonglong2 h0 = *(const ulonglong2*)(Hrd + 0 * H_ + koff + 4 * m);
                ulonglong2 h1 = *(const ulonglong2*)(Hrd + 1 * H_ + koff + 4 * m);
                ulonglong2 h2 = *(const ulonglong2*)(Hrd + 2 * H_ + koff + 4 * m);
                ulonglong2 h3 = *(const ulonglong2*)(Hrd + 3 * H_ + koff + 4 * m);
                a0[0] = fma2(h0.x, w[2 * m], a0[0]);
                a0[1] = fma2(h1.x, w[2 * m], a0[1]);
                a0[2] = fma2(h2.x, w[2 * m], a0[2]);
                a0[3] = fma2(h3.x, w[2 * m], a0[3]);
                a1[0] = fma2(h0.y, w[2 * m + 1], a1[0]);
                a1[1] = fma2(h1.y, w[2 * m + 1], a1[1]);
                a1[2] = fma2(h2.y, w[2 * m + 1], a1[2]);
                a1[3] = fma2(h3.y, w[2 * m + 1], a1[3]);
            }
            own_s0 = bsum + f2sum(a0[own0])     + f2sum(a1[own0]);
            own_s1 = bsum + f2sum(a0[own0 + 1]) + f2sum(a1[own0 + 1]);
            *PsW = make_float2(f2sum(a0[oth0])     + f2sum(a1[oth0]),
                               f2sum(a0[oth0 + 1]) + f2sum(a1[oth0 + 1]));
        }

        if (t >= 1) {
            // fc quarter-dots on h(t) (same stable Hrd buffer) -> out idx t-1
            u64 f0[4], f1[4];
#pragma unroll
            for (int r = 0; r < 4; r++) { f0[r] = 0ull; f1[r] = 0ull; }
#pragma unroll
            for (int m = 0; m < 8; m++) {
#pragma unroll
                for (int r = 0; r < 4; r++) {
                    ulonglong2 hv =
                        *(const ulonglong2*)(Hrd + r * H_ + 32 * q + 4 * m);
                    f0[r] = fma2(hv.x, fw[2 * m],     f0[r]);
                    f1[r] = fma2(hv.y, fw[2 * m + 1], f1[r]);
                }
            }
#pragma unroll
            for (int r = 0; r < 4; r++)
                Pfc[(r * 4 + q) * 64 + o] = f2sum(f0[r]) + f2sum(f1[r]);
        }

        __syncthreads();   // B

        // ================== post-barrier finalize ==================
        if (t < T_) {
            float2 p = *PsR;
            float hn0 = tanh_fast(own_s0 + p.x);
            float hn1 = tanh_fast(own_s1 + p.y);
            float* Hwr = Hs[cur ^ 1];
            Hwr[own0 * H_ + j]       = hn0;
            Hwr[(own0 + 1) * H_ + j] = hn1;
            if (is_loader) Xs[pr * 16 + pf] = xn;
        }
        if (t >= 1) {
            // combine quarters for (row rC, out o): conflict-free LDS
            float s = Pfc[(rC * 4 + 0) * 64 + o]
                    + Pfc[(rC * 4 + 1) * 64 + o]
                    + Pfc[(rC * 4 + 2) * 64 + o]
                    + Pfc[(rC * 4 + 3) * 64 + o];
            float y = fmaxf(s + b1, 0.f) * w2;
#pragma unroll
            for (int off = 16; off > 0; off >>= 1)
                y += __shfl_xor_sync(0xffffffffu, y, off);
            if (evenw) carry = y;                 // low-o half, kept in reg
            else if (lane == 0) red[rC] = y;      // high-o half -> smem
        }

        __syncthreads();   // A
        cur ^= 1;
    }

    // final output (T_-1): combined at iter T_, separated by barrier A
    if (evenw && lane == 0)
        outp[T_ - 1] = sigmoid_fast(carry + red[rC] + b2);
}

// ---------------------------------------------------------------------------

extern "C" void kernel_launch(void* const* d_in, const int* in_sizes, int n_in,
                              void* d_out, int out_size)
{
    const float* x     = (const float*)d_in[0];
    const float* W_ih  = (const float*)d_in[1];
    const float* W_hh  = (const float*)d_in[2];
    const float* b_ih  = (const float*)d_in[3];
    const float* b_hh  = (const float*)d_in[4];
    const float* fc1_w = (const float*)d_in[5];
    const float* fc1_b = (const float*)d_in[6];
    const float* fc2_w = (const float*)d_in[7];
    const float* fc2_b = (const float*)d_in[8];
    float* out = (float*)d_out;

    rnn_fused<<<128, NT>>>(x, W_ih, W_hh, b_ih, b_hh,
                           fc1_w, fc1_b, fc2_w, fc2_b, out);
}